// round 5
// baseline (speedup 1.0000x reference)
#include <cuda_runtime.h>
#include <cuda_fp16.h>
#include <cstdint>
#include <math.h>

#define DD   1024
#define SS   2048
#define NH   8
#define HDIM 128
#define BB   4

// ---------------- scratch (static device globals; no allocation) -------------
__device__ float  g_XLN32[8192 * 1024];
__device__ float  g_X232 [8192 * 1024];
__device__ __half g_XLN16[8192 * 1024];
__device__ __half g_X216 [8192 * 1024];
__device__ __half g_QKV16[(size_t)8192 * 3072];
__device__ __half g_CTX16[8192 * 1024];
__device__ __half g_W16  [(size_t)5 * 1024 * 1024];     // shiftW | inW | outW (fp16)

// ---------------- ptx helpers --------------------------------------------------
__device__ __forceinline__ uint32_t sptr(const void* p) {
    return (uint32_t)__cvta_generic_to_shared(p);
}
__device__ __forceinline__ void cp16(uint32_t s, const void* g) {
    asm volatile("cp.async.cg.shared.global [%0], [%1], 16;\n" :: "r"(s), "l"(g));
}
__device__ __forceinline__ void cp_commit() {
    asm volatile("cp.async.commit_group;\n");
}
__device__ __forceinline__ void ldsm_x4(uint32_t* r, uint32_t a) {
    asm volatile("ldmatrix.sync.aligned.m8n8.x4.shared.b16 {%0,%1,%2,%3}, [%4];\n"
                 : "=r"(r[0]), "=r"(r[1]), "=r"(r[2]), "=r"(r[3]) : "r"(a));
}
__device__ __forceinline__ void ldsm_x4_t(uint32_t* r, uint32_t a) {
    asm volatile("ldmatrix.sync.aligned.m8n8.x4.trans.shared.b16 {%0,%1,%2,%3}, [%4];\n"
                 : "=r"(r[0]), "=r"(r[1]), "=r"(r[2]), "=r"(r[3]) : "r"(a));
}
__device__ __forceinline__ void mma16816(float c[4], const uint32_t a[4], const uint32_t b[2]) {
    asm volatile(
        "mma.sync.aligned.m16n8k16.row.col.f32.f16.f16.f32 "
        "{%0,%1,%2,%3},{%4,%5,%6,%7},{%8,%9},{%0,%1,%2,%3};\n"
        : "+f"(c[0]), "+f"(c[1]), "+f"(c[2]), "+f"(c[3])
        : "r"(a[0]), "r"(a[1]), "r"(a[2]), "r"(a[3]), "r"(b[0]), "r"(b[1]));
}
__device__ __forceinline__ uint32_t packh2(float a, float b) {
    __half2 h = __floats2half2_rn(a, b);
    return *reinterpret_cast<uint32_t*>(&h);
}

// ---------------- f32 -> f16 convert ------------------------------------------
__global__ void f2h_kernel(const float* __restrict__ a, __half* __restrict__ o, int n4) {
    int i = blockIdx.x * 256 + threadIdx.x;
    if (i < n4) {
        float4 v = reinterpret_cast<const float4*>(a)[i];
        __half2* p = reinterpret_cast<__half2*>(o) + i * 2;
        p[0] = __floats2half2_rn(v.x, v.y);
        p[1] = __floats2half2_rn(v.z, v.w);
    }
}

// ---------------- fused per-token indexed LayerNorm ----------------------------
__global__ void ln_kernel(const float* __restrict__ x, const int* __restrict__ ts,
                          const float* __restrict__ gamma, const float* __restrict__ beta,
                          const float* __restrict__ decay, int T,
                          float* __restrict__ o32, __half* __restrict__ o16) {
    __shared__ float s1[8], s2[8];
    long row = blockIdx.x;
    int tid = threadIdx.x;
    float4 v = reinterpret_cast<const float4*>(x + row * DD)[tid];
    float s = v.x + v.y + v.z + v.w;
    float q = v.x * v.x + v.y * v.y + v.z * v.z + v.w * v.w;
    #pragma unroll
    for (int o = 16; o; o >>= 1) {
        s += __shfl_xor_sync(0xffffffffu, s, o);
        q += __shfl_xor_sync(0xffffffffu, q, o);
    }
    if ((tid & 31) == 0) { s1[tid >> 5] = s; s2[tid >> 5] = q; }
    __syncthreads();
    float Sm = 0.f, Qm = 0.f;
    #pragma unroll
    for (int i = 0; i < 8; i++) { Sm += s1[i]; Qm += s2[i]; }
    float mu   = Sm * (1.0f / DD);
    float var  = Qm * (1.0f / DD) - mu * mu;
    float rstd = rsqrtf(var + 1e-5f);

    int tv = ts[row];
    float4 o;
    if (tv < T) {
        int idx = tv < 0 ? 0 : tv;
        float4 gm = reinterpret_cast<const float4*>(gamma + (long)idx * DD)[tid];
        float4 bt = reinterpret_cast<const float4*>(beta  + (long)idx * DD)[tid];
        float dk = decay[idx];
        o.x = ((v.x - mu) * rstd * gm.x + bt.x) * dk;
        o.y = ((v.y - mu) * rstd * gm.y + bt.y) * dk;
        o.z = ((v.z - mu) * rstd * gm.z + bt.z) * dk;
        o.w = ((v.w - mu) * rstd * gm.w + bt.w) * dk;
    } else {
        o = v;
    }
    reinterpret_cast<float4*>(o32 + row * DD)[tid] = o;
    __half2* p = reinterpret_cast<__half2*>(o16 + row * DD) + tid * 2;
    p[0] = __floats2half2_rn(o.x, o.y);
    p[1] = __floats2half2_rn(o.z, o.w);
}

// ---------------- fp16 NT GEMM: 128x128 tile, warp 64x64, BK=64, 2-stage -------
// C[m,n] = sum_k A[m,k]*B[n,k] (+bias) (+Res).  A:[M,K] B:[N,K] row-major fp16.
#define BK   64
#define GLD  72                       // smem row stride in halves (144B)
#define GST  (128 * GLD)              // halves per (128 x BK) stage
#define GSMEM (4 * GST * 2)           // bytes: A0 A1 B0 B1

__global__ __launch_bounds__(128, 2)
void hgemm(const __half* __restrict__ A, int lda,
           const __half* __restrict__ B, int ldb,
           int ldc,
           float* __restrict__ C32, __half* __restrict__ C16,
           const float* __restrict__ bias,
           const float* __restrict__ Res, int ldres,
           int K)
{
    extern __shared__ __half sm[];
    __half* As = sm;                  // 2 stages
    __half* Bs = sm + 2 * GST;        // 2 stages

    const int m0 = blockIdx.y * 128;
    const int n0 = blockIdx.x * 128;

    const int tid  = threadIdx.x;
    const int warp = tid >> 5, lane = tid & 31;
    const int g = lane >> 2, t = lane & 3;
    const int wm = (warp >> 1) * 64;
    const int wn = (warp & 1) * 64;

    float c[4][8][4];
    #pragma unroll
    for (int i = 0; i < 4; i++)
        #pragma unroll
        for (int j = 0; j < 8; j++)
            #pragma unroll
            for (int r = 0; r < 4; r++) c[i][j][r] = 0.f;

    auto loadA = [&](int st, int k0) {
        #pragma unroll
        for (int i = 0; i < 8; i++) {
            int idx = tid + i * 128;           // 1024 chunks of 16B
            int r = idx >> 3, o = (idx & 7) * 8;
            cp16(sptr(&As[st * GST + r * GLD + o]), A + (long)(m0 + r) * lda + k0 + o);
        }
    };
    auto loadB = [&](int st, int k0) {
        #pragma unroll
        for (int i = 0; i < 8; i++) {
            int idx = tid + i * 128;
            int r = idx >> 3, o = (idx & 7) * 8;
            cp16(sptr(&Bs[st * GST + r * GLD + o]), B + (long)(n0 + r) * ldb + k0 + o);
        }
    };

    auto compute = [&](int st) {
        #pragma unroll
        for (int kk = 0; kk < BK; kk += 16) {
            uint32_t a[4][4], b[4][4];
            #pragma unroll
            for (int mi = 0; mi < 4; mi++)
                ldsm_x4(a[mi], sptr(&As[st * GST + (wm + mi * 16 + (lane & 15)) * GLD
                                        + kk + (lane >> 4) * 8]));
            #pragma unroll
            for (int ni = 0; ni < 4; ni++)
                ldsm_x4(b[ni], sptr(&Bs[st * GST + (wn + ni * 16 + (lane & 7) + ((lane >> 4) << 3)) * GLD
                                        + kk + ((lane >> 3) & 1) * 8]));
            #pragma unroll
            for (int mi = 0; mi < 4; mi++)
                #pragma unroll
                for (int ni = 0; ni < 4; ni++) {
                    mma16816(c[mi][2 * ni],     a[mi], b[ni]);
                    mma16816(c[mi][2 * ni + 1], a[mi], b[ni] + 2);
                }
        }
    };

    const int KT = K / BK;
    loadA(0, 0); loadB(0, 0); cp_commit();
    if (KT > 1) { loadA(1, BK); loadB(1, BK); cp_commit(); }
    int st = 0;
    for (int kt = 0; kt < KT; kt++) {
        if (kt + 1 < KT) asm volatile("cp.async.wait_group 1;\n");
        else             asm volatile("cp.async.wait_group 0;\n");
        __syncthreads();
        compute(st);
        __syncthreads();
        if (kt + 2 < KT) {
            loadA(st, (kt + 2) * BK); loadB(st, (kt + 2) * BK); cp_commit();
        }
        st ^= 1;
    }

    // ---- epilogue ----
    #pragma unroll
    for (int mi = 0; mi < 4; mi++) {
        #pragma unroll
        for (int nj = 0; nj < 8; nj++) {
            int row0 = m0 + wm + mi * 16 + g;
            int col  = n0 + wn + nj * 8 + 2 * t;
            float2 v0, v1;
            v0.x = c[mi][nj][0]; v0.y = c[mi][nj][1];
            v1.x = c[mi][nj][2]; v1.y = c[mi][nj][3];
            if (bias) {
                float b0 = bias[col], b1 = bias[col + 1];
                v0.x += b0; v0.y += b1; v1.x += b0; v1.y += b1;
            }
            if (Res) {
                v0.x += Res[(long)row0 * ldres + col];
                v0.y += Res[(long)row0 * ldres + col + 1];
                v1.x += Res[(long)(row0 + 8) * ldres + col];
                v1.y += Res[(long)(row0 + 8) * ldres + col + 1];
            }
            if (C32) {
                *reinterpret_cast<float2*>(&C32[(long)row0 * ldc + col])       = v0;
                *reinterpret_cast<float2*>(&C32[(long)(row0 + 8) * ldc + col]) = v1;
            }
            if (C16) {
                *reinterpret_cast<__half2*>(&C16[(long)row0 * ldc + col])       = __floats2half2_rn(v0.x, v0.y);
                *reinterpret_cast<__half2*>(&C16[(long)(row0 + 8) * ldc + col]) = __floats2half2_rn(v1.x, v1.y);
            }
        }
    }
}

// ---------------- flash attention (Q tile 128, KV tiles 128, online softmax) ----
#define FLD 136
#define FTILE (128 * FLD)
#define FSMEM (5 * FTILE * 2)

__global__ __launch_bounds__(256, 1)
void flash_kernel(const __half* __restrict__ QKV, __half* __restrict__ CTX) {
    extern __shared__ __half sm[];
    __half* Qs = sm;
    __half* Kb = sm + FTILE;
    __half* Vb = sm + 3 * FTILE;

    const int qt = blockIdx.x;
    const int h  = blockIdx.y;
    const int b  = blockIdx.z;
    const long base = (long)b * SS * 3 * DD + (long)h * HDIM;
    const __half* Qg = QKV + base;
    const __half* Kg = QKV + base + DD;
    const __half* Vg = QKV + base + 2 * DD;

    const int tid = threadIdx.x, warp = tid >> 5, lane = tid & 31;
    const int g = lane >> 2, t = lane & 3;

    auto loadK = [&](int j, int buf) {
        __half* dst = Kb + buf * FTILE;
        #pragma unroll
        for (int i = 0; i < 8; i++) {
            int ch = tid + i * 256;
            int r = ch >> 4, o = (ch & 15) * 8;
            cp16(sptr(&dst[r * FLD + o]), Kg + (long)(j * 128 + r) * (3 * DD) + o);
        }
    };
    auto loadV = [&](int j, int buf) {
        __half* dst = Vb + buf * FTILE;
        #pragma unroll
        for (int i = 0; i < 8; i++) {
            int ch = tid + i * 256;
            int r = ch >> 4, o = (ch & 15) * 8;
            cp16(sptr(&dst[r * FLD + o]), Vg + (long)(j * 128 + r) * (3 * DD) + o);
        }
    };

    #pragma unroll
    for (int i = 0; i < 8; i++) {
        int ch = tid + i * 256;
        int r = ch >> 4, o = (ch & 15) * 8;
        cp16(sptr(&Qs[r * FLD + o]), Qg + (long)(qt * 128 + r) * (3 * DD) + o);
    }
    cp_commit();
    loadK(0, 0); loadV(0, 0); cp_commit();
    loadK(1, 1); loadV(1, 1); cp_commit();

    asm volatile("cp.async.wait_group 2;\n");
    __syncthreads();

    uint32_t qf[8][4];
    const __half2 sc2 = __float2half2_rn(0.08838834764831845f);
    #pragma unroll
    for (int kt = 0; kt < 8; kt++) {
        ldsm_x4(qf[kt], sptr(&Qs[(warp * 16 + (lane & 15)) * FLD + kt * 16 + (lane >> 4) * 8]));
        #pragma unroll
        for (int r = 0; r < 4; r++) {
            __half2 v = *reinterpret_cast<__half2*>(&qf[kt][r]);
            v = __hmul2(v, sc2);
            qf[kt][r] = *reinterpret_cast<uint32_t*>(&v);
        }
    }

    float m0 = -1e30f, m1 = -1e30f, l0 = 0.f, l1 = 0.f;
    float o[16][4];
    #pragma unroll
    for (int i = 0; i < 16; i++)
        #pragma unroll
        for (int r = 0; r < 4; r++) o[i][r] = 0.f;

    const int NKV = SS / 128;
    for (int j = 0; j < NKV; j++) {
        const int buf = j & 1;
        if (j < NKV - 1) asm volatile("cp.async.wait_group 1;\n");
        else             asm volatile("cp.async.wait_group 0;\n");
        __syncthreads();

        float s[16][4];
        #pragma unroll
        for (int i = 0; i < 16; i++)
            #pragma unroll
            for (int r = 0; r < 4; r++) s[i][r] = 0.f;
        const __half* Ksb = Kb + buf * FTILE;
        #pragma unroll
        for (int n2 = 0; n2 < 8; n2++) {
            #pragma unroll
            for (int kk = 0; kk < 8; kk++) {
                uint32_t bf[4];
                ldsm_x4(bf, sptr(&Ksb[(n2 * 16 + (lane & 7) + ((lane >> 4) << 3)) * FLD
                                      + kk * 16 + ((lane >> 3) & 1) * 8]));
                mma16816(s[2 * n2],     qf[kk], bf);
                mma16816(s[2 * n2 + 1], qf[kk], bf + 2);
            }
        }

        float mx0 = -1e30f, mx1 = -1e30f;
        #pragma unroll
        for (int i = 0; i < 16; i++) {
            mx0 = fmaxf(mx0, fmaxf(s[i][0], s[i][1]));
            mx1 = fmaxf(mx1, fmaxf(s[i][2], s[i][3]));
        }
        mx0 = fmaxf(mx0, __shfl_xor_sync(0xffffffffu, mx0, 1));
        mx0 = fmaxf(mx0, __shfl_xor_sync(0xffffffffu, mx0, 2));
        mx1 = fmaxf(mx1, __shfl_xor_sync(0xffffffffu, mx1, 1));
        mx1 = fmaxf(mx1, __shfl_xor_sync(0xffffffffu, mx1, 2));
        float nm0 = fmaxf(m0, mx0), nm1 = fmaxf(m1, mx1);
        float rs0 = __expf(m0 - nm0), rs1 = __expf(m1 - nm1);
        float sum0 = 0.f, sum1 = 0.f;
        #pragma unroll
        for (int i = 0; i < 16; i++) {
            s[i][0] = __expf(s[i][0] - nm0);
            s[i][1] = __expf(s[i][1] - nm0);
            s[i][2] = __expf(s[i][2] - nm1);
            s[i][3] = __expf(s[i][3] - nm1);
            sum0 += s[i][0] + s[i][1];
            sum1 += s[i][2] + s[i][3];
        }
        sum0 += __shfl_xor_sync(0xffffffffu, sum0, 1);
        sum0 += __shfl_xor_sync(0xffffffffu, sum0, 2);
        sum1 += __shfl_xor_sync(0xffffffffu, sum1, 1);
        sum1 += __shfl_xor_sync(0xffffffffu, sum1, 2);
        l0 = l0 * rs0 + sum0;
        l1 = l1 * rs1 + sum1;
        m0 = nm0; m1 = nm1;
        #pragma unroll
        for (int i = 0; i < 16; i++) {
            o[i][0] *= rs0; o[i][1] *= rs0;
            o[i][2] *= rs1; o[i][3] *= rs1;
        }

        const __half* Vsb = Vb + buf * FTILE;
        #pragma unroll
        for (int kt = 0; kt < 8; kt++) {
            uint32_t a[4];
            a[0] = packh2(s[2 * kt][0],     s[2 * kt][1]);
            a[1] = packh2(s[2 * kt][2],     s[2 * kt][3]);
            a[2] = packh2(s[2 * kt + 1][0], s[2 * kt + 1][1]);
            a[3] = packh2(s[2 * kt + 1][2], s[2 * kt + 1][3]);
            #pragma unroll
            for (int n2 = 0; n2 < 8; n2++) {
                uint32_t bf[4];
                ldsm_x4_t(bf, sptr(&Vsb[(kt * 16 + (lane & 15)) * FLD
                                        + n2 * 16 + (lane >> 4) * 8]));
                mma16816(o[2 * n2],     a, bf);
                mma16816(o[2 * n2 + 1], a, bf + 2);
            }
        }

        __syncthreads();
        if (j + 2 < NKV) { loadK(j + 2, buf); loadV(j + 2, buf); cp_commit(); }
    }

    float inv0 = 1.0f / l0, inv1 = 1.0f / l1;
    __half* Cp = CTX + ((long)b * SS + qt * 128 + warp * 16) * DD + h * HDIM;
    #pragma unroll
    for (int i = 0; i < 16; i++) {
        int col = i * 8 + 2 * t;
        *reinterpret_cast<__half2*>(&Cp[(long)g * DD + col]) =
            __floats2half2_rn(o[i][0] * inv0, o[i][1] * inv0);
        *reinterpret_cast<__half2*>(&Cp[(long)(g + 8) * DD + col]) =
            __floats2half2_rn(o[i][2] * inv1, o[i][3] * inv1);
    }
}

// ---------------- launch --------------------------------------------------------
extern "C" void kernel_launch(void* const* d_in, const int* in_sizes, int n_in,
                              void* d_out, int out_size) {
    const float* x      = (const float*)d_in[0];
    const int*   ts     = (const int*)  d_in[1];
    const float* gamma  = (const float*)d_in[2];
    const float* beta   = (const float*)d_in[3];
    const float* decay  = (const float*)d_in[4];
    const float* shiftW = (const float*)d_in[5];
    const float* shiftb = (const float*)d_in[6];
    const float* inW    = (const float*)d_in[7];
    const float* inb    = (const float*)d_in[8];
    const float* outW   = (const float*)d_in[9];
    const float* outb   = (const float*)d_in[10];
    float* out = (float*)d_out;

    const int T  = in_sizes[4];
    const int BS = in_sizes[0] / DD;       // 8192

    float *XLN32, *X232;
    __half *XLN16, *X216, *QKV16, *CTX16, *W16;
    cudaGetSymbolAddress((void**)&XLN32, g_XLN32);
    cudaGetSymbolAddress((void**)&X232,  g_X232);
    cudaGetSymbolAddress((void**)&XLN16, g_XLN16);
    cudaGetSymbolAddress((void**)&X216,  g_X216);
    cudaGetSymbolAddress((void**)&QKV16, g_QKV16);
    cudaGetSymbolAddress((void**)&CTX16, g_CTX16);
    cudaGetSymbolAddress((void**)&W16,   g_W16);

    __half* shW16 = W16;
    __half* inW16 = W16 + (size_t)1024 * 1024;
    __half* otW16 = W16 + (size_t)4 * 1024 * 1024;

    cudaFuncSetAttribute(flash_kernel, cudaFuncAttributeMaxDynamicSharedMemorySize, FSMEM);
    cudaFuncSetAttribute(hgemm,        cudaFuncAttributeMaxDynamicSharedMemorySize, GSMEM);

    // 0) weights -> fp16
    f2h_kernel<<<(1024 * 1024 / 4 + 255) / 256, 256>>>(shiftW, shW16, 1024 * 1024 / 4);
    f2h_kernel<<<(3072 * 1024 / 4 + 255) / 256, 256>>>(inW,    inW16, 3072 * 1024 / 4);
    f2h_kernel<<<(1024 * 1024 / 4 + 255) / 256, 256>>>(outW,   otW16, 1024 * 1024 / 4);

    // 1) indexed LayerNorm
    ln_kernel<<<BS, 256>>>(x, ts, gamma, beta, decay, T, XLN32, XLN16);

    // 2) X2 = XLN + XLN @ shiftW^T + shiftb
    hgemm<<<dim3(DD / 128, BS / 128), 128, GSMEM>>>(
        XLN16, DD,  shW16, DD,  DD,  X232, X216,  shiftb,  XLN32, DD,  DD);

    // 3) QKV = X2 @ inW^T + inb
    hgemm<<<dim3(3 * DD / 128, BS / 128), 128, GSMEM>>>(
        X216, DD,  inW16, DD,  3 * DD,  nullptr, QKV16,  inb,  nullptr, 0,  DD);

    // 4) fused flash attention
    flash_kernel<<<dim3(SS / 128, NH, BB), 256, FSMEM>>>(QKV16, CTX16);

    // 5) out = X2 + CTX @ outW^T + outb
    hgemm<<<dim3(DD / 128, BS / 128), 128, GSMEM>>>(
        CTX16, DD,  otW16, DD,  DD,  out, nullptr,  outb,  X232, DD,  DD);
}

// round 6
// speedup vs baseline: 1.2388x; 1.2388x over previous
#include <cuda_runtime.h>
#include <cuda_fp16.h>
#include <cstdint>
#include <math.h>

#define DD   1024
#define SS   2048
#define NH   8
#define HDIM 128
#define BB   4

// ---------------- scratch (static device globals; no allocation) -------------
__device__ float  g_XLN32[8192 * 1024];
__device__ float  g_X232 [8192 * 1024];
__device__ __half g_XLN16[8192 * 1024];
__device__ __half g_X216 [8192 * 1024];
__device__ __half g_QKV16[(size_t)8192 * 3072];
__device__ __half g_CTX16[8192 * 1024];
__device__ __half g_W16  [(size_t)5 * 1024 * 1024];     // shiftW | inW | outW (fp16)

// ---------------- ptx helpers --------------------------------------------------
__device__ __forceinline__ uint32_t sptr(const void* p) {
    return (uint32_t)__cvta_generic_to_shared(p);
}
__device__ __forceinline__ void cp16(uint32_t s, const void* g) {
    asm volatile("cp.async.cg.shared.global [%0], [%1], 16;\n" :: "r"(s), "l"(g));
}
__device__ __forceinline__ void cp_commit() {
    asm volatile("cp.async.commit_group;\n");
}
__device__ __forceinline__ void ldsm_x4(uint32_t* r, uint32_t a) {
    asm volatile("ldmatrix.sync.aligned.m8n8.x4.shared.b16 {%0,%1,%2,%3}, [%4];\n"
                 : "=r"(r[0]), "=r"(r[1]), "=r"(r[2]), "=r"(r[3]) : "r"(a));
}
__device__ __forceinline__ void ldsm_x4_t(uint32_t* r, uint32_t a) {
    asm volatile("ldmatrix.sync.aligned.m8n8.x4.trans.shared.b16 {%0,%1,%2,%3}, [%4];\n"
                 : "=r"(r[0]), "=r"(r[1]), "=r"(r[2]), "=r"(r[3]) : "r"(a));
}
__device__ __forceinline__ void mma16816(float c[4], const uint32_t a[4], const uint32_t b[2]) {
    asm volatile(
        "mma.sync.aligned.m16n8k16.row.col.f32.f16.f16.f32 "
        "{%0,%1,%2,%3},{%4,%5,%6,%7},{%8,%9},{%0,%1,%2,%3};\n"
        : "+f"(c[0]), "+f"(c[1]), "+f"(c[2]), "+f"(c[3])
        : "r"(a[0]), "r"(a[1]), "r"(a[2]), "r"(a[3]), "r"(b[0]), "r"(b[1]));
}
__device__ __forceinline__ uint32_t packh2(float a, float b) {
    __half2 h = __floats2half2_rn(a, b);
    return *reinterpret_cast<uint32_t*>(&h);
}

// ---------------- f32 -> f16 convert ------------------------------------------
__global__ void f2h_kernel(const float* __restrict__ a, __half* __restrict__ o, int n4) {
    int i = blockIdx.x * 256 + threadIdx.x;
    if (i < n4) {
        float4 v = reinterpret_cast<const float4*>(a)[i];
        __half2* p = reinterpret_cast<__half2*>(o) + i * 2;
        p[0] = __floats2half2_rn(v.x, v.y);
        p[1] = __floats2half2_rn(v.z, v.w);
    }
}

// ---------------- fused per-token indexed LayerNorm ----------------------------
__global__ void ln_kernel(const float* __restrict__ x, const int* __restrict__ ts,
                          const float* __restrict__ gamma, const float* __restrict__ beta,
                          const float* __restrict__ decay, int T,
                          float* __restrict__ o32, __half* __restrict__ o16) {
    __shared__ float s1[8], s2[8];
    long row = blockIdx.x;
    int tid = threadIdx.x;
    float4 v = reinterpret_cast<const float4*>(x + row * DD)[tid];
    float s = v.x + v.y + v.z + v.w;
    float q = v.x * v.x + v.y * v.y + v.z * v.z + v.w * v.w;
    #pragma unroll
    for (int o = 16; o; o >>= 1) {
        s += __shfl_xor_sync(0xffffffffu, s, o);
        q += __shfl_xor_sync(0xffffffffu, q, o);
    }
    if ((tid & 31) == 0) { s1[tid >> 5] = s; s2[tid >> 5] = q; }
    __syncthreads();
    float Sm = 0.f, Qm = 0.f;
    #pragma unroll
    for (int i = 0; i < 8; i++) { Sm += s1[i]; Qm += s2[i]; }
    float mu   = Sm * (1.0f / DD);
    float var  = Qm * (1.0f / DD) - mu * mu;
    float rstd = rsqrtf(var + 1e-5f);

    int tv = ts[row];
    float4 o;
    if (tv < T) {
        int idx = tv < 0 ? 0 : tv;
        float4 gm = reinterpret_cast<const float4*>(gamma + (long)idx * DD)[tid];
        float4 bt = reinterpret_cast<const float4*>(beta  + (long)idx * DD)[tid];
        float dk = decay[idx];
        o.x = ((v.x - mu) * rstd * gm.x + bt.x) * dk;
        o.y = ((v.y - mu) * rstd * gm.y + bt.y) * dk;
        o.z = ((v.z - mu) * rstd * gm.z + bt.z) * dk;
        o.w = ((v.w - mu) * rstd * gm.w + bt.w) * dk;
    } else {
        o = v;
    }
    reinterpret_cast<float4*>(o32 + row * DD)[tid] = o;
    __half2* p = reinterpret_cast<__half2*>(o16 + row * DD) + tid * 2;
    p[0] = __floats2half2_rn(o.x, o.y);
    p[1] = __floats2half2_rn(o.z, o.w);
}

// ---------------- fp16 GEMM (R3 known-good: 128x128x32, 256 thr, 2 CTA/SM) -----
#define BM 128
#define BN 128
#define BK 32
#define ALD 40

__global__ __launch_bounds__(256, 2)
void hgemm(const __half* __restrict__ A, int lda,
           const __half* __restrict__ B, int ldb,
           int ldc,
           float* __restrict__ C32, __half* __restrict__ C16,
           const float* __restrict__ bias,
           const float* __restrict__ Res, int ldres,
           float alpha, int K)
{
    __shared__ alignas(16) __half As[2][BM * ALD];
    __shared__ alignas(16) __half Bs[2][BM * ALD];

    const int m0 = blockIdx.y * BM;
    const int n0 = blockIdx.x * BN;

    const int tid  = threadIdx.x;
    const int warp = tid >> 5, lane = tid & 31;
    const int g = lane >> 2, t = lane & 3;
    const int wm = (warp >> 2) * 64;
    const int wn = (warp & 3) * 32;

    float c[4][4][4];
    #pragma unroll
    for (int i = 0; i < 4; i++)
        #pragma unroll
        for (int j = 0; j < 4; j++)
            #pragma unroll
            for (int r = 0; r < 4; r++) c[i][j][r] = 0.f;

    auto loadA = [&](int st, int k0) {
        #pragma unroll
        for (int i = 0; i < 2; i++) {
            int ch = tid + i * 256;
            int r = ch >> 2, o = (ch & 3) * 8;
            cp16(sptr(&As[st][r * ALD + o]), A + (long)(m0 + r) * lda + k0 + o);
        }
    };
    auto loadB = [&](int st, int k0) {
        #pragma unroll
        for (int i = 0; i < 2; i++) {
            int ch = tid + i * 256;
            int r = ch >> 2, o = (ch & 3) * 8;
            cp16(sptr(&Bs[st][r * ALD + o]), B + (long)(n0 + r) * ldb + k0 + o);
        }
    };

    auto compute = [&](int st) {
        #pragma unroll
        for (int kk = 0; kk < BK; kk += 16) {
            uint32_t a[4][4];
            #pragma unroll
            for (int mi = 0; mi < 4; mi++)
                ldsm_x4(a[mi], sptr(&As[st][(wm + mi * 16 + (lane & 15)) * ALD
                                            + kk + (lane >> 4) * 8]));
            uint32_t b[2][4];
            #pragma unroll
            for (int nt = 0; nt < 2; nt++)
                ldsm_x4(b[nt], sptr(&Bs[st][(wn + nt * 16 + (lane & 7) + ((lane >> 4) << 3)) * ALD
                                            + kk + ((lane >> 3) & 1) * 8]));
            #pragma unroll
            for (int mi = 0; mi < 4; mi++)
                #pragma unroll
                for (int ni = 0; ni < 4; ni++)
                    mma16816(c[mi][ni], a[mi], &b[ni >> 1][(ni & 1) * 2]);
        }
    };

    const int KT = K / BK;
    loadA(0, 0); loadB(0, 0); cp_commit();
    int st = 0;
    for (int kt = 0; kt < KT; kt++) {
        if (kt + 1 < KT) {
            loadA(st ^ 1, (kt + 1) * BK); loadB(st ^ 1, (kt + 1) * BK); cp_commit();
            asm volatile("cp.async.wait_group 1;\n");
        } else {
            asm volatile("cp.async.wait_group 0;\n");
        }
        __syncthreads();
        compute(st);
        __syncthreads();
        st ^= 1;
    }

    #pragma unroll
    for (int mi = 0; mi < 4; mi++) {
        #pragma unroll
        for (int ni = 0; ni < 4; ni++) {
            int row0 = m0 + wm + mi * 16 + g;
            int col  = n0 + wn + ni * 8 + 2 * t;
            float2 v0, v1;
            v0.x = c[mi][ni][0] * alpha; v0.y = c[mi][ni][1] * alpha;
            v1.x = c[mi][ni][2] * alpha; v1.y = c[mi][ni][3] * alpha;
            if (bias) {
                float b0 = bias[col], b1 = bias[col + 1];
                v0.x += b0; v0.y += b1; v1.x += b0; v1.y += b1;
            }
            if (Res) {
                v0.x += Res[(long)row0 * ldres + col];
                v0.y += Res[(long)row0 * ldres + col + 1];
                v1.x += Res[(long)(row0 + 8) * ldres + col];
                v1.y += Res[(long)(row0 + 8) * ldres + col + 1];
            }
            if (C32) {
                *reinterpret_cast<float2*>(&C32[(long)row0 * ldc + col])       = v0;
                *reinterpret_cast<float2*>(&C32[(long)(row0 + 8) * ldc + col]) = v1;
            }
            if (C16) {
                *reinterpret_cast<__half2*>(&C16[(long)row0 * ldc + col])       = __floats2half2_rn(v0.x, v0.y);
                *reinterpret_cast<__half2*>(&C16[(long)(row0 + 8) * ldc + col]) = __floats2half2_rn(v1.x, v1.y);
            }
        }
    }
}

// ---------------- flash attention: Q tile 64, KV tiles 64, 128 thr, 2 CTA/SM ----
#define FLD 136
#define FT64 (64 * FLD)                 // halves per 64x128 tile
#define FSMEM64 (5 * FT64 * 2)          // bytes: Q + 2xK + 2xV = 87040

__global__ __launch_bounds__(128, 2)
void flash_kernel(const __half* __restrict__ QKV, __half* __restrict__ CTX) {
    extern __shared__ __half sm[];
    __half* Qs = sm;                       // [64][FLD]
    __half* Kb = sm + FT64;                // 2 buffers of [64][FLD]
    __half* Vb = sm + 3 * FT64;            // 2 buffers

    const int qt = blockIdx.x;             // 32 tiles of 64 rows
    const int h  = blockIdx.y;
    const int b  = blockIdx.z;
    const long base = (long)b * SS * 3 * DD + (long)h * HDIM;
    const __half* Qg = QKV + base;
    const __half* Kg = QKV + base + DD;
    const __half* Vg = QKV + base + 2 * DD;

    const int tid = threadIdx.x, warp = tid >> 5, lane = tid & 31;
    const int g = lane >> 2, t = lane & 3;

    auto loadK = [&](int j, int buf) {
        __half* dst = Kb + buf * FT64;
        #pragma unroll
        for (int i = 0; i < 8; i++) {
            int ch = tid + i * 128;            // 1024 chunks: 64 rows x 16
            int r = ch >> 4, o = (ch & 15) * 8;
            cp16(sptr(&dst[r * FLD + o]), Kg + (long)(j * 64 + r) * (3 * DD) + o);
        }
    };
    auto loadV = [&](int j, int buf) {
        __half* dst = Vb + buf * FT64;
        #pragma unroll
        for (int i = 0; i < 8; i++) {
            int ch = tid + i * 128;
            int r = ch >> 4, o = (ch & 15) * 8;
            cp16(sptr(&dst[r * FLD + o]), Vg + (long)(j * 64 + r) * (3 * DD) + o);
        }
    };

    // stage Q (64 rows), prefetch KV0, KV1
    #pragma unroll
    for (int i = 0; i < 8; i++) {
        int ch = tid + i * 128;
        int r = ch >> 4, o = (ch & 15) * 8;
        cp16(sptr(&Qs[r * FLD + o]), Qg + (long)(qt * 64 + r) * (3 * DD) + o);
    }
    cp_commit();
    loadK(0, 0); loadV(0, 0); cp_commit();
    loadK(1, 1); loadV(1, 1); cp_commit();

    asm volatile("cp.async.wait_group 2;\n");
    __syncthreads();

    // Q fragments (pre-scaled)
    uint32_t qf[8][4];
    const __half2 sc2 = __float2half2_rn(0.08838834764831845f);
    #pragma unroll
    for (int kt = 0; kt < 8; kt++) {
        ldsm_x4(qf[kt], sptr(&Qs[(warp * 16 + (lane & 15)) * FLD + kt * 16 + (lane >> 4) * 8]));
        #pragma unroll
        for (int r = 0; r < 4; r++) {
            __half2 v = *reinterpret_cast<__half2*>(&qf[kt][r]);
            v = __hmul2(v, sc2);
            qf[kt][r] = *reinterpret_cast<uint32_t*>(&v);
        }
    }

    float m0 = -1e30f, m1 = -1e30f, l0 = 0.f, l1 = 0.f;
    float o[16][4];
    #pragma unroll
    for (int i = 0; i < 16; i++)
        #pragma unroll
        for (int r = 0; r < 4; r++) o[i][r] = 0.f;

    const int NKV = SS / 64;   // 32
    for (int j = 0; j < NKV; j++) {
        const int buf = j & 1;
        if (j < NKV - 1) asm volatile("cp.async.wait_group 1;\n");
        else             asm volatile("cp.async.wait_group 0;\n");
        __syncthreads();

        // ---- S = Qscaled @ K^T  (64 cols) ----
        float s[8][4];
        #pragma unroll
        for (int i = 0; i < 8; i++)
            #pragma unroll
            for (int r = 0; r < 4; r++) s[i][r] = 0.f;
        const __half* Ksb = Kb + buf * FT64;
        #pragma unroll
        for (int n2 = 0; n2 < 4; n2++) {
            #pragma unroll
            for (int kk = 0; kk < 8; kk++) {
                uint32_t bf[4];
                ldsm_x4(bf, sptr(&Ksb[(n2 * 16 + (lane & 7) + ((lane >> 4) << 3)) * FLD
                                      + kk * 16 + ((lane >> 3) & 1) * 8]));
                mma16816(s[2 * n2],     qf[kk], bf);
                mma16816(s[2 * n2 + 1], qf[kk], bf + 2);
            }
        }

        // ---- online softmax ----
        float mx0 = -1e30f, mx1 = -1e30f;
        #pragma unroll
        for (int i = 0; i < 8; i++) {
            mx0 = fmaxf(mx0, fmaxf(s[i][0], s[i][1]));
            mx1 = fmaxf(mx1, fmaxf(s[i][2], s[i][3]));
        }
        mx0 = fmaxf(mx0, __shfl_xor_sync(0xffffffffu, mx0, 1));
        mx0 = fmaxf(mx0, __shfl_xor_sync(0xffffffffu, mx0, 2));
        mx1 = fmaxf(mx1, __shfl_xor_sync(0xffffffffu, mx1, 1));
        mx1 = fmaxf(mx1, __shfl_xor_sync(0xffffffffu, mx1, 2));
        float nm0 = fmaxf(m0, mx0), nm1 = fmaxf(m1, mx1);
        float rs0 = __expf(m0 - nm0), rs1 = __expf(m1 - nm1);
        float sum0 = 0.f, sum1 = 0.f;
        #pragma unroll
        for (int i = 0; i < 8; i++) {
            s[i][0] = __expf(s[i][0] - nm0);
            s[i][1] = __expf(s[i][1] - nm0);
            s[i][2] = __expf(s[i][2] - nm1);
            s[i][3] = __expf(s[i][3] - nm1);
            sum0 += s[i][0] + s[i][1];
            sum1 += s[i][2] + s[i][3];
        }
        sum0 += __shfl_xor_sync(0xffffffffu, sum0, 1);
        sum0 += __shfl_xor_sync(0xffffffffu, sum0, 2);
        sum1 += __shfl_xor_sync(0xffffffffu, sum1, 1);
        sum1 += __shfl_xor_sync(0xffffffffu, sum1, 2);
        l0 = l0 * rs0 + sum0;
        l1 = l1 * rs1 + sum1;
        m0 = nm0; m1 = nm1;
        #pragma unroll
        for (int i = 0; i < 16; i++) {
            o[i][0] *= rs0; o[i][1] *= rs0;
            o[i][2] *= rs1; o[i][3] *= rs1;
        }

        // ---- O += P @ V  (P is 64 wide -> 4 k16 steps) ----
        const __half* Vsb = Vb + buf * FT64;
        #pragma unroll
        for (int kt = 0; kt < 4; kt++) {
            uint32_t a[4];
            a[0] = packh2(s[2 * kt][0],     s[2 * kt][1]);
            a[1] = packh2(s[2 * kt][2],     s[2 * kt][3]);
            a[2] = packh2(s[2 * kt + 1][0], s[2 * kt + 1][1]);
            a[3] = packh2(s[2 * kt + 1][2], s[2 * kt + 1][3]);
            #pragma unroll
            for (int n2 = 0; n2 < 8; n2++) {
                uint32_t bf[4];
                ldsm_x4_t(bf, sptr(&Vsb[(kt * 16 + (lane & 15)) * FLD
                                        + n2 * 16 + (lane >> 4) * 8]));
                mma16816(o[2 * n2],     a, bf);
                mma16816(o[2 * n2 + 1], a, bf + 2);
            }
        }

        __syncthreads();
        if (j + 2 < NKV) { loadK(j + 2, buf); loadV(j + 2, buf); cp_commit(); }
    }

    // ---- epilogue ----
    float inv0 = 1.0f / l0, inv1 = 1.0f / l1;
    __half* Cp = CTX + ((long)b * SS + qt * 64 + warp * 16) * DD + h * HDIM;
    #pragma unroll
    for (int i = 0; i < 16; i++) {
        int col = i * 8 + 2 * t;
        *reinterpret_cast<__half2*>(&Cp[(long)g * DD + col]) =
            __floats2half2_rn(o[i][0] * inv0, o[i][1] * inv0);
        *reinterpret_cast<__half2*>(&Cp[(long)(g + 8) * DD + col]) =
            __floats2half2_rn(o[i][2] * inv1, o[i][3] * inv1);
    }
}

// ---------------- launch --------------------------------------------------------
extern "C" void kernel_launch(void* const* d_in, const int* in_sizes, int n_in,
                              void* d_out, int out_size) {
    const float* x      = (const float*)d_in[0];
    const int*   ts     = (const int*)  d_in[1];
    const float* gamma  = (const float*)d_in[2];
    const float* beta   = (const float*)d_in[3];
    const float* decay  = (const float*)d_in[4];
    const float* shiftW = (const float*)d_in[5];
    const float* shiftb = (const float*)d_in[6];
    const float* inW    = (const float*)d_in[7];
    const float* inb    = (const float*)d_in[8];
    const float* outW   = (const float*)d_in[9];
    const float* outb   = (const float*)d_in[10];
    float* out = (float*)d_out;

    const int T  = in_sizes[4];
    const int BS = in_sizes[0] / DD;       // 8192

    float *XLN32, *X232;
    __half *XLN16, *X216, *QKV16, *CTX16, *W16;
    cudaGetSymbolAddress((void**)&XLN32, g_XLN32);
    cudaGetSymbolAddress((void**)&X232,  g_X232);
    cudaGetSymbolAddress((void**)&XLN16, g_XLN16);
    cudaGetSymbolAddress((void**)&X216,  g_X216);
    cudaGetSymbolAddress((void**)&QKV16, g_QKV16);
    cudaGetSymbolAddress((void**)&CTX16, g_CTX16);
    cudaGetSymbolAddress((void**)&W16,   g_W16);

    __half* shW16 = W16;
    __half* inW16 = W16 + (size_t)1024 * 1024;
    __half* otW16 = W16 + (size_t)4 * 1024 * 1024;

    cudaFuncSetAttribute(flash_kernel, cudaFuncAttributeMaxDynamicSharedMemorySize, FSMEM64);

    // 0) weights -> fp16
    f2h_kernel<<<(1024 * 1024 / 4 + 255) / 256, 256>>>(shiftW, shW16, 1024 * 1024 / 4);
    f2h_kernel<<<(3072 * 1024 / 4 + 255) / 256, 256>>>(inW,    inW16, 3072 * 1024 / 4);
    f2h_kernel<<<(1024 * 1024 / 4 + 255) / 256, 256>>>(outW,   otW16, 1024 * 1024 / 4);

    // 1) indexed LayerNorm
    ln_kernel<<<BS, 256>>>(x, ts, gamma, beta, decay, T, XLN32, XLN16);

    // 2) X2 = XLN + XLN @ shiftW^T + shiftb
    hgemm<<<dim3(DD / BN, BS / BM), 256>>>(
        XLN16, DD,  shW16, DD,  DD,  X232, X216,  shiftb,  XLN32, DD,  1.0f, DD);

    // 3) QKV = X2 @ inW^T + inb
    hgemm<<<dim3(3 * DD / BN, BS / BM), 256>>>(
        X216, DD,  inW16, DD,  3 * DD,  nullptr, QKV16,  inb,  nullptr, 0,  1.0f, DD);

    // 4) fused flash attention (Q tiles of 64 rows, 2 CTAs/SM)
    flash_kernel<<<dim3(SS / 64, NH, BB), 128, FSMEM64>>>(QKV16, CTX16);

    // 5) out = X2 + CTX @ outW^T + outb
    hgemm<<<dim3(DD / BN, BS / BM), 256>>>(
        CTX16, DD,  otW16, DD,  DD,  out, nullptr,  outb,  X232, DD,  1.0f, DD);
}

// round 7
// speedup vs baseline: 1.3444x; 1.0852x over previous
#include <cuda_runtime.h>
#include <cuda_fp16.h>
#include <cstdint>
#include <math.h>

#define DD   1024
#define SS   2048
#define NH   8
#define HDIM 128
#define BB   4

// ---------------- scratch (static device globals; no allocation) -------------
__device__ float  g_XLN32[8192 * 1024];
__device__ float  g_X232 [8192 * 1024];
__device__ __half g_XLN16[8192 * 1024];
__device__ __half g_X216 [8192 * 1024];
__device__ __half g_QKV16[(size_t)8192 * 3072];
__device__ __half g_CTX16[8192 * 1024];
__device__ __half g_W16  [(size_t)5 * 1024 * 1024];     // shiftW | inW | outW (fp16)

// ---------------- ptx helpers --------------------------------------------------
__device__ __forceinline__ uint32_t sptr(const void* p) {
    return (uint32_t)__cvta_generic_to_shared(p);
}
__device__ __forceinline__ void cp16(uint32_t s, const void* g) {
    asm volatile("cp.async.cg.shared.global [%0], [%1], 16;\n" :: "r"(s), "l"(g));
}
__device__ __forceinline__ void cp_commit() {
    asm volatile("cp.async.commit_group;\n");
}
__device__ __forceinline__ void ldsm_x4(uint32_t* r, uint32_t a) {
    asm volatile("ldmatrix.sync.aligned.m8n8.x4.shared.b16 {%0,%1,%2,%3}, [%4];\n"
                 : "=r"(r[0]), "=r"(r[1]), "=r"(r[2]), "=r"(r[3]) : "r"(a));
}
__device__ __forceinline__ void ldsm_x4_t(uint32_t* r, uint32_t a) {
    asm volatile("ldmatrix.sync.aligned.m8n8.x4.trans.shared.b16 {%0,%1,%2,%3}, [%4];\n"
                 : "=r"(r[0]), "=r"(r[1]), "=r"(r[2]), "=r"(r[3]) : "r"(a));
}
__device__ __forceinline__ void mma16816(float c[4], const uint32_t a[4], const uint32_t b[2]) {
    asm volatile(
        "mma.sync.aligned.m16n8k16.row.col.f32.f16.f16.f32 "
        "{%0,%1,%2,%3},{%4,%5,%6,%7},{%8,%9},{%0,%1,%2,%3};\n"
        : "+f"(c[0]), "+f"(c[1]), "+f"(c[2]), "+f"(c[3])
        : "r"(a[0]), "r"(a[1]), "r"(a[2]), "r"(a[3]), "r"(b[0]), "r"(b[1]));
}
__device__ __forceinline__ uint32_t packh2(float a, float b) {
    __half2 h = __floats2half2_rn(a, b);
    return *reinterpret_cast<uint32_t*>(&h);
}

// ---------------- f32 -> f16 convert ------------------------------------------
__global__ void f2h_kernel(const float* __restrict__ a, __half* __restrict__ o, int n4) {
    int i = blockIdx.x * 256 + threadIdx.x;
    if (i < n4) {
        float4 v = reinterpret_cast<const float4*>(a)[i];
        __half2* p = reinterpret_cast<__half2*>(o) + i * 2;
        p[0] = __floats2half2_rn(v.x, v.y);
        p[1] = __floats2half2_rn(v.z, v.w);
    }
}

// ---------------- fused per-token indexed LayerNorm ----------------------------
__global__ void ln_kernel(const float* __restrict__ x, const int* __restrict__ ts,
                          const float* __restrict__ gamma, const float* __restrict__ beta,
                          const float* __restrict__ decay, int T,
                          float* __restrict__ o32, __half* __restrict__ o16) {
    __shared__ float s1[8], s2[8];
    long row = blockIdx.x;
    int tid = threadIdx.x;
    float4 v = reinterpret_cast<const float4*>(x + row * DD)[tid];
    float s = v.x + v.y + v.z + v.w;
    float q = v.x * v.x + v.y * v.y + v.z * v.z + v.w * v.w;
    #pragma unroll
    for (int o = 16; o; o >>= 1) {
        s += __shfl_xor_sync(0xffffffffu, s, o);
        q += __shfl_xor_sync(0xffffffffu, q, o);
    }
    if ((tid & 31) == 0) { s1[tid >> 5] = s; s2[tid >> 5] = q; }
    __syncthreads();
    float Sm = 0.f, Qm = 0.f;
    #pragma unroll
    for (int i = 0; i < 8; i++) { Sm += s1[i]; Qm += s2[i]; }
    float mu   = Sm * (1.0f / DD);
    float var  = Qm * (1.0f / DD) - mu * mu;
    float rstd = rsqrtf(var + 1e-5f);

    int tv = ts[row];
    float4 o;
    if (tv < T) {
        int idx = tv < 0 ? 0 : tv;
        float4 gm = reinterpret_cast<const float4*>(gamma + (long)idx * DD)[tid];
        float4 bt = reinterpret_cast<const float4*>(beta  + (long)idx * DD)[tid];
        float dk = decay[idx];
        o.x = ((v.x - mu) * rstd * gm.x + bt.x) * dk;
        o.y = ((v.y - mu) * rstd * gm.y + bt.y) * dk;
        o.z = ((v.z - mu) * rstd * gm.z + bt.z) * dk;
        o.w = ((v.w - mu) * rstd * gm.w + bt.w) * dk;
    } else {
        o = v;
    }
    reinterpret_cast<float4*>(o32 + row * DD)[tid] = o;
    __half2* p = reinterpret_cast<__half2*>(o16 + row * DD) + tid * 2;
    p[0] = __floats2half2_rn(o.x, o.y);
    p[1] = __floats2half2_rn(o.z, o.w);
}

// ---------------- fp16 GEMM: 128x128x32, 256 thr, 4-stage, 1 sync/tile ---------
#define BM 128
#define BN 128
#define BK 32
#define ALD 40
#define NSTG 4
#define ASTG (BM * ALD)                 // halves per A (or B) stage
#define GSMEM (NSTG * 2 * ASTG * 2)     // bytes = 81920

__global__ __launch_bounds__(256, 2)
void hgemm(const __half* __restrict__ A, int lda,
           const __half* __restrict__ B, int ldb,
           int ldc,
           float* __restrict__ C32, __half* __restrict__ C16,
           const float* __restrict__ bias,
           const float* __restrict__ Res, int ldres,
           float alpha, int K)
{
    extern __shared__ __half sm[];
    __half* As = sm;                    // NSTG stages
    __half* Bs = sm + NSTG * ASTG;      // NSTG stages

    const int m0 = blockIdx.y * BM;
    const int n0 = blockIdx.x * BN;

    const int tid  = threadIdx.x;
    const int warp = tid >> 5, lane = tid & 31;
    const int g = lane >> 2, t = lane & 3;
    const int wm = (warp >> 2) * 64;
    const int wn = (warp & 3) * 32;

    float c[4][4][4];
    #pragma unroll
    for (int i = 0; i < 4; i++)
        #pragma unroll
        for (int j = 0; j < 4; j++)
            #pragma unroll
            for (int r = 0; r < 4; r++) c[i][j][r] = 0.f;

    auto loadAB = [&](int st, int k0) {
        #pragma unroll
        for (int i = 0; i < 2; i++) {
            int ch = tid + i * 256;
            int r = ch >> 2, o = (ch & 3) * 8;
            cp16(sptr(&As[st * ASTG + r * ALD + o]), A + (long)(m0 + r) * lda + k0 + o);
        }
        #pragma unroll
        for (int i = 0; i < 2; i++) {
            int ch = tid + i * 256;
            int r = ch >> 2, o = (ch & 3) * 8;
            cp16(sptr(&Bs[st * ASTG + r * ALD + o]), B + (long)(n0 + r) * ldb + k0 + o);
        }
    };

    auto compute = [&](int st) {
        #pragma unroll
        for (int kk = 0; kk < BK; kk += 16) {
            uint32_t a[4][4];
            #pragma unroll
            for (int mi = 0; mi < 4; mi++)
                ldsm_x4(a[mi], sptr(&As[st * ASTG + (wm + mi * 16 + (lane & 15)) * ALD
                                        + kk + (lane >> 4) * 8]));
            uint32_t b[2][4];
            #pragma unroll
            for (int nt = 0; nt < 2; nt++)
                ldsm_x4(b[nt], sptr(&Bs[st * ASTG + (wn + nt * 16 + (lane & 7) + ((lane >> 4) << 3)) * ALD
                                        + kk + ((lane >> 3) & 1) * 8]));
            #pragma unroll
            for (int mi = 0; mi < 4; mi++)
                #pragma unroll
                for (int ni = 0; ni < 4; ni++)
                    mma16816(c[mi][ni], a[mi], &b[ni >> 1][(ni & 1) * 2]);
        }
    };

    const int KT = K / BK;
    // prologue: fill 3 of 4 stages
    #pragma unroll
    for (int p = 0; p < NSTG - 1; p++) {
        if (p < KT) { loadAB(p, p * BK); }
        cp_commit();
    }

    for (int kt = 0; kt < KT; kt++) {
        const int rem = KT - 1 - kt;          // loads still outstanding beyond this tile
        if (rem >= 2)      asm volatile("cp.async.wait_group 2;\n");
        else if (rem == 1) asm volatile("cp.async.wait_group 1;\n");
        else               asm volatile("cp.async.wait_group 0;\n");
        __syncthreads();                      // single barrier per k-tile
        compute(kt & (NSTG - 1));
        if (kt + NSTG - 1 < KT) {
            loadAB((kt + NSTG - 1) & (NSTG - 1), (kt + NSTG - 1) * BK);
            cp_commit();
        } else {
            cp_commit();                      // keep group count in step
        }
    }

    // ---- epilogue ----
    #pragma unroll
    for (int mi = 0; mi < 4; mi++) {
        #pragma unroll
        for (int ni = 0; ni < 4; ni++) {
            int row0 = m0 + wm + mi * 16 + g;
            int col  = n0 + wn + ni * 8 + 2 * t;
            float2 v0, v1;
            v0.x = c[mi][ni][0] * alpha; v0.y = c[mi][ni][1] * alpha;
            v1.x = c[mi][ni][2] * alpha; v1.y = c[mi][ni][3] * alpha;
            if (bias) {
                float b0 = bias[col], b1 = bias[col + 1];
                v0.x += b0; v0.y += b1; v1.x += b0; v1.y += b1;
            }
            if (Res) {
                v0.x += Res[(long)row0 * ldres + col];
                v0.y += Res[(long)row0 * ldres + col + 1];
                v1.x += Res[(long)(row0 + 8) * ldres + col];
                v1.y += Res[(long)(row0 + 8) * ldres + col + 1];
            }
            if (C32) {
                *reinterpret_cast<float2*>(&C32[(long)row0 * ldc + col])       = v0;
                *reinterpret_cast<float2*>(&C32[(long)(row0 + 8) * ldc + col]) = v1;
            }
            if (C16) {
                *reinterpret_cast<__half2*>(&C16[(long)row0 * ldc + col])       = __floats2half2_rn(v0.x, v0.y);
                *reinterpret_cast<__half2*>(&C16[(long)(row0 + 8) * ldc + col]) = __floats2half2_rn(v1.x, v1.y);
            }
        }
    }
}

// ---------------- flash attention: Q tile 64, KV tiles 64, 128 thr, 2 CTA/SM ----
#define FLD 136
#define FT64 (64 * FLD)                 // halves per 64x128 tile
#define FSMEM64 (5 * FT64 * 2)          // bytes: Q + 2xK + 2xV = 87040

__global__ __launch_bounds__(128, 2)
void flash_kernel(const __half* __restrict__ QKV, __half* __restrict__ CTX) {
    extern __shared__ __half sm[];
    __half* Qs = sm;                       // [64][FLD]
    __half* Kb = sm + FT64;                // 2 buffers of [64][FLD]
    __half* Vb = sm + 3 * FT64;            // 2 buffers

    const int qt = blockIdx.x;             // 32 tiles of 64 rows
    const int h  = blockIdx.y;
    const int b  = blockIdx.z;
    const long base = (long)b * SS * 3 * DD + (long)h * HDIM;
    const __half* Qg = QKV + base;
    const __half* Kg = QKV + base + DD;
    const __half* Vg = QKV + base + 2 * DD;

    const int tid = threadIdx.x, warp = tid >> 5, lane = tid & 31;
    const int g = lane >> 2, t = lane & 3;

    auto loadK = [&](int j, int buf) {
        __half* dst = Kb + buf * FT64;
        #pragma unroll
        for (int i = 0; i < 8; i++) {
            int ch = tid + i * 128;            // 1024 chunks: 64 rows x 16
            int r = ch >> 4, o = (ch & 15) * 8;
            cp16(sptr(&dst[r * FLD + o]), Kg + (long)(j * 64 + r) * (3 * DD) + o);
        }
    };
    auto loadV = [&](int j, int buf) {
        __half* dst = Vb + buf * FT64;
        #pragma unroll
        for (int i = 0; i < 8; i++) {
            int ch = tid + i * 128;
            int r = ch >> 4, o = (ch & 15) * 8;
            cp16(sptr(&dst[r * FLD + o]), Vg + (long)(j * 64 + r) * (3 * DD) + o);
        }
    };

    // stage Q (64 rows), prefetch KV0, KV1
    #pragma unroll
    for (int i = 0; i < 8; i++) {
        int ch = tid + i * 128;
        int r = ch >> 4, o = (ch & 15) * 8;
        cp16(sptr(&Qs[r * FLD + o]), Qg + (long)(qt * 64 + r) * (3 * DD) + o);
    }
    cp_commit();
    loadK(0, 0); loadV(0, 0); cp_commit();
    loadK(1, 1); loadV(1, 1); cp_commit();

    asm volatile("cp.async.wait_group 2;\n");
    __syncthreads();

    // Q fragments (pre-scaled)
    uint32_t qf[8][4];
    const __half2 sc2 = __float2half2_rn(0.08838834764831845f);
    #pragma unroll
    for (int kt = 0; kt < 8; kt++) {
        ldsm_x4(qf[kt], sptr(&Qs[(warp * 16 + (lane & 15)) * FLD + kt * 16 + (lane >> 4) * 8]));
        #pragma unroll
        for (int r = 0; r < 4; r++) {
            __half2 v = *reinterpret_cast<__half2*>(&qf[kt][r]);
            v = __hmul2(v, sc2);
            qf[kt][r] = *reinterpret_cast<uint32_t*>(&v);
        }
    }

    float m0 = -1e30f, m1 = -1e30f, l0 = 0.f, l1 = 0.f;
    float o[16][4];
    #pragma unroll
    for (int i = 0; i < 16; i++)
        #pragma unroll
        for (int r = 0; r < 4; r++) o[i][r] = 0.f;

    const int NKV = SS / 64;   // 32
    for (int j = 0; j < NKV; j++) {
        const int buf = j & 1;
        if (j < NKV - 1) asm volatile("cp.async.wait_group 1;\n");
        else             asm volatile("cp.async.wait_group 0;\n");
        __syncthreads();

        // ---- S = Qscaled @ K^T  (64 cols) ----
        float s[8][4];
        #pragma unroll
        for (int i = 0; i < 8; i++)
            #pragma unroll
            for (int r = 0; r < 4; r++) s[i][r] = 0.f;
        const __half* Ksb = Kb + buf * FT64;
        #pragma unroll
        for (int n2 = 0; n2 < 4; n2++) {
            #pragma unroll
            for (int kk = 0; kk < 8; kk++) {
                uint32_t bf[4];
                ldsm_x4(bf, sptr(&Ksb[(n2 * 16 + (lane & 7) + ((lane >> 4) << 3)) * FLD
                                      + kk * 16 + ((lane >> 3) & 1) * 8]));
                mma16816(s[2 * n2],     qf[kk], bf);
                mma16816(s[2 * n2 + 1], qf[kk], bf + 2);
            }
        }

        // ---- online softmax ----
        float mx0 = -1e30f, mx1 = -1e30f;
        #pragma unroll
        for (int i = 0; i < 8; i++) {
            mx0 = fmaxf(mx0, fmaxf(s[i][0], s[i][1]));
            mx1 = fmaxf(mx1, fmaxf(s[i][2], s[i][3]));
        }
        mx0 = fmaxf(mx0, __shfl_xor_sync(0xffffffffu, mx0, 1));
        mx0 = fmaxf(mx0, __shfl_xor_sync(0xffffffffu, mx0, 2));
        mx1 = fmaxf(mx1, __shfl_xor_sync(0xffffffffu, mx1, 1));
        mx1 = fmaxf(mx1, __shfl_xor_sync(0xffffffffu, mx1, 2));
        float nm0 = fmaxf(m0, mx0), nm1 = fmaxf(m1, mx1);
        float rs0 = __expf(m0 - nm0), rs1 = __expf(m1 - nm1);
        float sum0 = 0.f, sum1 = 0.f;
        #pragma unroll
        for (int i = 0; i < 8; i++) {
            s[i][0] = __expf(s[i][0] - nm0);
            s[i][1] = __expf(s[i][1] - nm0);
            s[i][2] = __expf(s[i][2] - nm1);
            s[i][3] = __expf(s[i][3] - nm1);
            sum0 += s[i][0] + s[i][1];
            sum1 += s[i][2] + s[i][3];
        }
        sum0 += __shfl_xor_sync(0xffffffffu, sum0, 1);
        sum0 += __shfl_xor_sync(0xffffffffu, sum0, 2);
        sum1 += __shfl_xor_sync(0xffffffffu, sum1, 1);
        sum1 += __shfl_xor_sync(0xffffffffu, sum1, 2);
        l0 = l0 * rs0 + sum0;
        l1 = l1 * rs1 + sum1;
        m0 = nm0; m1 = nm1;
        #pragma unroll
        for (int i = 0; i < 16; i++) {
            o[i][0] *= rs0; o[i][1] *= rs0;
            o[i][2] *= rs1; o[i][3] *= rs1;
        }

        // ---- O += P @ V  (P is 64 wide -> 4 k16 steps) ----
        const __half* Vsb = Vb + buf * FT64;
        #pragma unroll
        for (int kt = 0; kt < 4; kt++) {
            uint32_t a[4];
            a[0] = packh2(s[2 * kt][0],     s[2 * kt][1]);
            a[1] = packh2(s[2 * kt][2],     s[2 * kt][3]);
            a[2] = packh2(s[2 * kt + 1][0], s[2 * kt + 1][1]);
            a[3] = packh2(s[2 * kt + 1][2], s[2 * kt + 1][3]);
            #pragma unroll
            for (int n2 = 0; n2 < 8; n2++) {
                uint32_t bf[4];
                ldsm_x4_t(bf, sptr(&Vsb[(kt * 16 + (lane & 15)) * FLD
                                        + n2 * 16 + (lane >> 4) * 8]));
                mma16816(o[2 * n2],     a, bf);
                mma16816(o[2 * n2 + 1], a, bf + 2);
            }
        }

        __syncthreads();
        if (j + 2 < NKV) { loadK(j + 2, buf); loadV(j + 2, buf); cp_commit(); }
    }

    // ---- epilogue ----
    float inv0 = 1.0f / l0, inv1 = 1.0f / l1;
    __half* Cp = CTX + ((long)b * SS + qt * 64 + warp * 16) * DD + h * HDIM;
    #pragma unroll
    for (int i = 0; i < 16; i++) {
        int col = i * 8 + 2 * t;
        *reinterpret_cast<__half2*>(&Cp[(long)g * DD + col]) =
            __floats2half2_rn(o[i][0] * inv0, o[i][1] * inv0);
        *reinterpret_cast<__half2*>(&Cp[(long)(g + 8) * DD + col]) =
            __floats2half2_rn(o[i][2] * inv1, o[i][3] * inv1);
    }
}

// ---------------- launch --------------------------------------------------------
extern "C" void kernel_launch(void* const* d_in, const int* in_sizes, int n_in,
                              void* d_out, int out_size) {
    const float* x      = (const float*)d_in[0];
    const int*   ts     = (const int*)  d_in[1];
    const float* gamma  = (const float*)d_in[2];
    const float* beta   = (const float*)d_in[3];
    const float* decay  = (const float*)d_in[4];
    const float* shiftW = (const float*)d_in[5];
    const float* shiftb = (const float*)d_in[6];
    const float* inW    = (const float*)d_in[7];
    const float* inb    = (const float*)d_in[8];
    const float* outW   = (const float*)d_in[9];
    const float* outb   = (const float*)d_in[10];
    float* out = (float*)d_out;

    const int T  = in_sizes[4];
    const int BS = in_sizes[0] / DD;       // 8192

    float *XLN32, *X232;
    __half *XLN16, *X216, *QKV16, *CTX16, *W16;
    cudaGetSymbolAddress((void**)&XLN32, g_XLN32);
    cudaGetSymbolAddress((void**)&X232,  g_X232);
    cudaGetSymbolAddress((void**)&XLN16, g_XLN16);
    cudaGetSymbolAddress((void**)&X216,  g_X216);
    cudaGetSymbolAddress((void**)&QKV16, g_QKV16);
    cudaGetSymbolAddress((void**)&CTX16, g_CTX16);
    cudaGetSymbolAddress((void**)&W16,   g_W16);

    __half* shW16 = W16;
    __half* inW16 = W16 + (size_t)1024 * 1024;
    __half* otW16 = W16 + (size_t)4 * 1024 * 1024;

    cudaFuncSetAttribute(flash_kernel, cudaFuncAttributeMaxDynamicSharedMemorySize, FSMEM64);
    cudaFuncSetAttribute(hgemm,        cudaFuncAttributeMaxDynamicSharedMemorySize, GSMEM);

    // 0) weights -> fp16
    f2h_kernel<<<(1024 * 1024 / 4 + 255) / 256, 256>>>(shiftW, shW16, 1024 * 1024 / 4);
    f2h_kernel<<<(3072 * 1024 / 4 + 255) / 256, 256>>>(inW,    inW16, 3072 * 1024 / 4);
    f2h_kernel<<<(1024 * 1024 / 4 + 255) / 256, 256>>>(outW,   otW16, 1024 * 1024 / 4);

    // 1) indexed LayerNorm
    ln_kernel<<<BS, 256>>>(x, ts, gamma, beta, decay, T, XLN32, XLN16);

    // 2) X2 = XLN + XLN @ shiftW^T + shiftb
    hgemm<<<dim3(DD / BN, BS / BM), 256, GSMEM>>>(
        XLN16, DD,  shW16, DD,  DD,  X232, X216,  shiftb,  XLN32, DD,  1.0f, DD);

    // 3) QKV = X2 @ inW^T + inb
    hgemm<<<dim3(3 * DD / BN, BS / BM), 256, GSMEM>>>(
        X216, DD,  inW16, DD,  3 * DD,  nullptr, QKV16,  inb,  nullptr, 0,  1.0f, DD);

    // 4) fused flash attention (Q tiles of 64 rows, 2 CTAs/SM)
    flash_kernel<<<dim3(SS / 64, NH, BB), 128, FSMEM64>>>(QKV16, CTX16);

    // 5) out = X2 + CTX @ outW^T + outb
    hgemm<<<dim3(DD / BN, BS / BM), 256, GSMEM>>>(
        CTX16, DD,  otW16, DD,  DD,  out, nullptr,  outb,  X232, DD,  1.0f, DD);
}